// round 3
// baseline (speedup 1.0000x reference)
#include <cuda_runtime.h>
#include <cuda_bf16.h>
#include <cstdint>

// Koopman rollout: B=4096, T=64, K=192 (128 complex + 64 real), DT=0.01
// Persistent CTA design: 128 CTAs x 32 rows, all 64 steps in one launch.
// Weights in SMEM as packed bf16x2 (pairs along k), fp32 accum via fma.rn.f32x2.

#define SMEM_BYTES 193024

__device__ __forceinline__ unsigned long long bf2f2(unsigned w) {
    // bf16x2 (lo = even k, hi = odd k) -> packed f32x2
    unsigned lo = w << 16;
    unsigned hi = w & 0xFFFF0000u;
    unsigned long long r;
    asm("mov.b64 %0, {%1, %2};" : "=l"(r) : "r"(lo), "r"(hi));
    return r;
}
__device__ __forceinline__ void ffma2(unsigned long long& d, unsigned long long a,
                                      unsigned long long b) {
    asm("fma.rn.f32x2 %0, %1, %2, %0;" : "+l"(d) : "l"(a), "l"(b));
}
__device__ __forceinline__ unsigned long long pack2(float a, float b) {
    unsigned long long r;
    asm("mov.b64 %0, {%1, %2};" : "=l"(r) : "f"(a), "f"(b));
    return r;
}
__device__ __forceinline__ float hsum2(unsigned long long v) {
    float a, b;
    asm("mov.b64 {%0, %1}, %2;" : "=f"(a), "=f"(b) : "l"(v));
    return a + b;
}

__global__ void __launch_bounds__(256, 1)
koopman_kernel(const float* __restrict__ x,
               const float* __restrict__ cW1, const float* __restrict__ cb1,
               const float* __restrict__ cW2, const float* __restrict__ cb2,
               const float* __restrict__ rW1, const float* __restrict__ rb1,
               const float* __restrict__ rW2, const float* __restrict__ rb2,
               float* __restrict__ out)
{
    extern __shared__ unsigned char smem[];
    // layout (bytes):
    unsigned* w1  = (unsigned*)(smem);            // [192][98] bf16x2 (cW1 rows 0..127, rW1 128..191)
    unsigned* w2c = (unsigned*)(smem + 75264);    // [128][66] bf16x2
    unsigned* w2r = (unsigned*)(smem + 109056);   // [64][34]  bf16x2
    float* b1   = (float*)(smem + 117760);        // [192]
    float* b2   = (float*)(smem + 118528);        // [192]
    float* ysm  = (float*)(smem + 119296);        // [32][192] state
    float* h1sm = (float*)(smem + 143872);        // [32][192] relu(layer1)
    float* h2sm = (float*)(smem + 168448);        // [32][192] layer2 out

    const int tid = threadIdx.x;
    const int tx = tid & 31;
    const int ty = tid >> 5;        // 0..7
    const int row0 = ty * 4;        // 4 rows per thread
    const int rowg0 = blockIdx.x * 32;

    // ---- one-time: pack weights to bf16x2 in SMEM ----
    for (int idx = tid; idx < 192 * 96; idx += 256) {
        int j = idx / 96, p = idx - j * 96;
        const float* s = (j < 128) ? (cW1 + j * 192 + 2 * p)
                                   : (rW1 + (j - 128) * 192 + 2 * p);
        unsigned lo = __bfloat16_as_ushort(__float2bfloat16_rn(s[0]));
        unsigned hi = __bfloat16_as_ushort(__float2bfloat16_rn(s[1]));
        w1[j * 98 + p] = lo | (hi << 16);
    }
    for (int idx = tid; idx < 128 * 64; idx += 256) {
        int j = idx >> 6, p = idx & 63;
        const float* s = cW2 + j * 128 + 2 * p;
        unsigned lo = __bfloat16_as_ushort(__float2bfloat16_rn(s[0]));
        unsigned hi = __bfloat16_as_ushort(__float2bfloat16_rn(s[1]));
        w2c[j * 66 + p] = lo | (hi << 16);
    }
    for (int idx = tid; idx < 64 * 32; idx += 256) {
        int j = idx >> 5, p = idx & 31;
        const float* s = rW2 + j * 64 + 2 * p;
        unsigned lo = __bfloat16_as_ushort(__float2bfloat16_rn(s[0]));
        unsigned hi = __bfloat16_as_ushort(__float2bfloat16_rn(s[1]));
        w2r[j * 34 + p] = lo | (hi << 16);
    }
    if (tid < 192) {
        b1[tid] = (tid < 128) ? cb1[tid] : rb1[tid - 128];
        b2[tid] = (tid < 128) ? cb2[tid] : rb2[tid - 128];
    }
    // initial state y = x[:, 0, :]
    for (int idx = tid; idx < 32 * 192; idx += 256) {
        int r = idx / 192, k = idx - r * 192;
        ysm[idx] = x[(size_t)(rowg0 + r) * (64 * 192) + k];
    }
    __syncthreads();

    // per-thread precomputed pointers (constant across t)
    const unsigned* w1p[6];
    const unsigned* w2p[4];
    const unsigned* wrp[2];
#pragma unroll
    for (int m = 0; m < 6; ++m) w1p[m] = w1 + (tx + 32 * m) * 98;
#pragma unroll
    for (int m = 0; m < 4; ++m) w2p[m] = w2c + (tx + 32 * m) * 66;
#pragma unroll
    for (int m = 0; m < 2; ++m) wrp[m] = w2r + (tx + 32 * m) * 34;
    float* yr[4];
    float* h1r[4];
    float* h2r[4];
#pragma unroll
    for (int i = 0; i < 4; ++i) {
        yr[i]  = ysm  + (row0 + i) * 192;
        h1r[i] = h1sm + (row0 + i) * 192;
        h2r[i] = h2sm + (row0 + i) * 192;
    }

    for (int t = 0; t < 64; ++t) {
        // ===== Phase A: h1 = relu(y @ W1cat^T + b1cat)  (192 outputs, K=192) =====
        unsigned long long acc[4][6];
#pragma unroll
        for (int i = 0; i < 4; ++i)
#pragma unroll
            for (int m = 0; m < 6; ++m) acc[i][m] = 0ull;

#pragma unroll 4
        for (int kp = 0; kp < 48; ++kp) {   // k = 4*kp .. 4*kp+3
            unsigned long long ya[4], yb[4];
#pragma unroll
            for (int i = 0; i < 4; ++i) {
                float4 v = *(const float4*)(yr[i] + 4 * kp);
                ya[i] = pack2(v.x, v.y);
                yb[i] = pack2(v.z, v.w);
            }
#pragma unroll
            for (int m = 0; m < 6; ++m) {
                uint2 w = *(const uint2*)(w1p[m] + 2 * kp);
                unsigned long long wa = bf2f2(w.x);
                unsigned long long wb = bf2f2(w.y);
#pragma unroll
                for (int i = 0; i < 4; ++i) {
                    ffma2(acc[i][m], wa, ya[i]);
                    ffma2(acc[i][m], wb, yb[i]);
                }
            }
        }
#pragma unroll
        for (int m = 0; m < 6; ++m) {
            int f = tx + 32 * m;
            float bb = b1[f];
#pragma unroll
            for (int i = 0; i < 4; ++i)
                h1r[i][f] = fmaxf(hsum2(acc[i][m]) + bb, 0.0f);
        }
        __syncthreads();

        // ===== Phase B: h2 = h1[:, :128] @ cW2^T + cb2 ; r2 = h1[:,128:] @ rW2^T + rb2 =====
        unsigned long long acc2[4][6];
#pragma unroll
        for (int i = 0; i < 4; ++i)
#pragma unroll
            for (int m = 0; m < 6; ++m) acc2[i][m] = 0ull;

#pragma unroll 4
        for (int kp = 0; kp < 32; ++kp) {   // complex head, k = 4*kp
            unsigned long long ya[4], yb[4];
#pragma unroll
            for (int i = 0; i < 4; ++i) {
                float4 v = *(const float4*)(h1r[i] + 4 * kp);
                ya[i] = pack2(v.x, v.y);
                yb[i] = pack2(v.z, v.w);
            }
#pragma unroll
            for (int m = 0; m < 4; ++m) {
                uint2 w = *(const uint2*)(w2p[m] + 2 * kp);
                unsigned long long wa = bf2f2(w.x);
                unsigned long long wb = bf2f2(w.y);
#pragma unroll
                for (int i = 0; i < 4; ++i) {
                    ffma2(acc2[i][m], wa, ya[i]);
                    ffma2(acc2[i][m], wb, yb[i]);
                }
            }
        }
#pragma unroll 4
        for (int kp = 0; kp < 16; ++kp) {   // real head, k = 4*kp over h1 cols 128..191
            unsigned long long ya[4], yb[4];
#pragma unroll
            for (int i = 0; i < 4; ++i) {
                float4 v = *(const float4*)(h1r[i] + 128 + 4 * kp);
                ya[i] = pack2(v.x, v.y);
                yb[i] = pack2(v.z, v.w);
            }
#pragma unroll
            for (int m = 0; m < 2; ++m) {
                uint2 w = *(const uint2*)(wrp[m] + 2 * kp);
                unsigned long long wa = bf2f2(w.x);
                unsigned long long wb = bf2f2(w.y);
#pragma unroll
                for (int i = 0; i < 4; ++i) {
                    ffma2(acc2[i][4 + m], wa, ya[i]);
                    ffma2(acc2[i][4 + m], wb, yb[i]);
                }
            }
        }
#pragma unroll
        for (int m = 0; m < 6; ++m) {
            int f = tx + 32 * m;
            float bb = b2[f];
#pragma unroll
            for (int i = 0; i < 4; ++i)
                h2r[i][f] = hsum2(acc2[i][m]) + bb;
        }
        __syncthreads();

        // ===== Elementwise: rotate/scale complex pairs, scale reals; write y and out =====
#pragma unroll
        for (int i = 0; i < 4; ++i) {
            float* orow = out + ((size_t)(rowg0 + row0 + i) * 64 + t) * 192;
#pragma unroll
            for (int m = 0; m < 2; ++m) {
                int j2 = 2 * (tx + 32 * m);   // even feature of com pair
                float2 mo = *(const float2*)(h2r[i] + j2);   // (mu, omega)
                float2 yc = *(const float2*)(yr[i] + j2);    // (ye, yo)
                float e = __expf(0.01f * mo.x);
                float s, c;
                __sincosf(0.01f * mo.y, &s, &c);
                float2 nv;
                nv.x = e * (c * yc.x - s * yc.y);
                nv.y = e * (s * yc.x + c * yc.y);
                *(float2*)(yr[i] + j2) = nv;
                *(float2*)(orow + j2) = nv;
            }
#pragma unroll
            for (int m = 0; m < 2; ++m) {
                int f = 128 + tx + 32 * m;
                float nv = yr[i][f] * __expf(0.01f * h2r[i][f]);
                yr[i][f] = nv;
                orow[f] = nv;
            }
        }
        __syncthreads();
    }
}

extern "C" void kernel_launch(void* const* d_in, const int* in_sizes, int n_in,
                              void* d_out, int out_size)
{
    (void)in_sizes; (void)n_in; (void)out_size;
    cudaFuncSetAttribute(koopman_kernel,
                         cudaFuncAttributeMaxDynamicSharedMemorySize, SMEM_BYTES);
    koopman_kernel<<<128, 256, SMEM_BYTES>>>(
        (const float*)d_in[0],
        (const float*)d_in[1], (const float*)d_in[2],
        (const float*)d_in[3], (const float*)d_in[4],
        (const float*)d_in[5], (const float*)d_in[6],
        (const float*)d_in[7], (const float*)d_in[8],
        (float*)d_out);
}

// round 5
// speedup vs baseline: 1.0034x; 1.0034x over previous
#include <cuda_runtime.h>
#include <cuda_bf16.h>
#include <cstdint>

// Koopman rollout: B=4096, T=64, K=192 (128 complex + 64 real), DT=0.01
// Persistent CTA design: 128 CTAs x 32 rows, all 64 steps in one launch.
// Weights in SMEM as packed bf16x2 (pairs along k), fp32 accum via fma.rn.f32x2.

#define SMEM_BYTES 193024

__device__ __forceinline__ unsigned long long bf2f2(unsigned w) {
    // bf16x2 (lo = even k, hi = odd k) -> packed f32x2
    unsigned lo = w << 16;
    unsigned hi = w & 0xFFFF0000u;
    unsigned long long r;
    asm("mov.b64 %0, {%1, %2};" : "=l"(r) : "r"(lo), "r"(hi));
    return r;
}
__device__ __forceinline__ void ffma2(unsigned long long& d, unsigned long long a,
                                      unsigned long long b) {
    asm("fma.rn.f32x2 %0, %1, %2, %0;" : "+l"(d) : "l"(a), "l"(b));
}
__device__ __forceinline__ unsigned long long pack2(float a, float b) {
    unsigned long long r;
    asm("mov.b64 %0, {%1, %2};" : "=l"(r) : "f"(a), "f"(b));
    return r;
}
__device__ __forceinline__ float hsum2(unsigned long long v) {
    float a, b;
    asm("mov.b64 {%0, %1}, %2;" : "=f"(a), "=f"(b) : "l"(v));
    return a + b;
}

__global__ void __launch_bounds__(256, 1)
koopman_kernel(const float* __restrict__ x,
               const float* __restrict__ cW1, const float* __restrict__ cb1,
               const float* __restrict__ cW2, const float* __restrict__ cb2,
               const float* __restrict__ rW1, const float* __restrict__ rb1,
               const float* __restrict__ rW2, const float* __restrict__ rb2,
               float* __restrict__ out)
{
    extern __shared__ unsigned char smem[];
    // layout (bytes):
    unsigned* w1  = (unsigned*)(smem);            // [192][98] bf16x2 (cW1 rows 0..127, rW1 128..191)
    unsigned* w2c = (unsigned*)(smem + 75264);    // [128][66] bf16x2
    unsigned* w2r = (unsigned*)(smem + 109056);   // [64][34]  bf16x2
    float* b1   = (float*)(smem + 117760);        // [192]
    float* b2   = (float*)(smem + 118528);        // [192]
    float* ysm  = (float*)(smem + 119296);        // [32][192] state
    float* h1sm = (float*)(smem + 143872);        // [32][192] relu(layer1)
    float* h2sm = (float*)(smem + 168448);        // [32][192] layer2 out

    const int tid = threadIdx.x;
    const int tx = tid & 31;
    const int ty = tid >> 5;        // 0..7
    const int row0 = ty * 4;        // 4 rows per thread
    const int rowg0 = blockIdx.x * 32;

    // ---- one-time: pack weights to bf16x2 in SMEM ----
    for (int idx = tid; idx < 192 * 96; idx += 256) {
        int j = idx / 96, p = idx - j * 96;
        const float* s = (j < 128) ? (cW1 + j * 192 + 2 * p)
                                   : (rW1 + (j - 128) * 192 + 2 * p);
        unsigned lo = __bfloat16_as_ushort(__float2bfloat16_rn(s[0]));
        unsigned hi = __bfloat16_as_ushort(__float2bfloat16_rn(s[1]));
        w1[j * 98 + p] = lo | (hi << 16);
    }
    for (int idx = tid; idx < 128 * 64; idx += 256) {
        int j = idx >> 6, p = idx & 63;
        const float* s = cW2 + j * 128 + 2 * p;
        unsigned lo = __bfloat16_as_ushort(__float2bfloat16_rn(s[0]));
        unsigned hi = __bfloat16_as_ushort(__float2bfloat16_rn(s[1]));
        w2c[j * 66 + p] = lo | (hi << 16);
    }
    for (int idx = tid; idx < 64 * 32; idx += 256) {
        int j = idx >> 5, p = idx & 31;
        const float* s = rW2 + j * 64 + 2 * p;
        unsigned lo = __bfloat16_as_ushort(__float2bfloat16_rn(s[0]));
        unsigned hi = __bfloat16_as_ushort(__float2bfloat16_rn(s[1]));
        w2r[j * 34 + p] = lo | (hi << 16);
    }
    if (tid < 192) {
        b1[tid] = (tid < 128) ? cb1[tid] : rb1[tid - 128];
        b2[tid] = (tid < 128) ? cb2[tid] : rb2[tid - 128];
    }
    // initial state y = x[:, 0, :]
    for (int idx = tid; idx < 32 * 192; idx += 256) {
        int r = idx / 192, k = idx - r * 192;
        ysm[idx] = x[(size_t)(rowg0 + r) * (64 * 192) + k];
    }
    __syncthreads();

    // per-thread precomputed pointers (constant across t)
    const unsigned* w1p[6];
    const unsigned* w2p[4];
    const unsigned* wrp[2];
#pragma unroll
    for (int m = 0; m < 6; ++m) w1p[m] = w1 + (tx + 32 * m) * 98;
#pragma unroll
    for (int m = 0; m < 4; ++m) w2p[m] = w2c + (tx + 32 * m) * 66;
#pragma unroll
    for (int m = 0; m < 2; ++m) wrp[m] = w2r + (tx + 32 * m) * 34;
    float* yr[4];
    float* h1r[4];
    float* h2r[4];
#pragma unroll
    for (int i = 0; i < 4; ++i) {
        yr[i]  = ysm  + (row0 + i) * 192;
        h1r[i] = h1sm + (row0 + i) * 192;
        h2r[i] = h2sm + (row0 + i) * 192;
    }

    for (int t = 0; t < 64; ++t) {
        // ===== Phase A: h1 = relu(y @ W1cat^T + b1cat)  (192 outputs, K=192) =====
        unsigned long long acc[4][6];
#pragma unroll
        for (int i = 0; i < 4; ++i)
#pragma unroll
            for (int m = 0; m < 6; ++m) acc[i][m] = 0ull;

#pragma unroll 4
        for (int kp = 0; kp < 48; ++kp) {   // k = 4*kp .. 4*kp+3
            unsigned long long ya[4], yb[4];
#pragma unroll
            for (int i = 0; i < 4; ++i) {
                float4 v = *(const float4*)(yr[i] + 4 * kp);
                ya[i] = pack2(v.x, v.y);
                yb[i] = pack2(v.z, v.w);
            }
#pragma unroll
            for (int m = 0; m < 6; ++m) {
                uint2 w = *(const uint2*)(w1p[m] + 2 * kp);
                unsigned long long wa = bf2f2(w.x);
                unsigned long long wb = bf2f2(w.y);
#pragma unroll
                for (int i = 0; i < 4; ++i) {
                    ffma2(acc[i][m], wa, ya[i]);
                    ffma2(acc[i][m], wb, yb[i]);
                }
            }
        }
#pragma unroll
        for (int m = 0; m < 6; ++m) {
            int f = tx + 32 * m;
            float bb = b1[f];
#pragma unroll
            for (int i = 0; i < 4; ++i)
                h1r[i][f] = fmaxf(hsum2(acc[i][m]) + bb, 0.0f);
        }
        __syncthreads();

        // ===== Phase B: h2 = h1[:, :128] @ cW2^T + cb2 ; r2 = h1[:,128:] @ rW2^T + rb2 =====
        unsigned long long acc2[4][6];
#pragma unroll
        for (int i = 0; i < 4; ++i)
#pragma unroll
            for (int m = 0; m < 6; ++m) acc2[i][m] = 0ull;

#pragma unroll 4
        for (int kp = 0; kp < 32; ++kp) {   // complex head, k = 4*kp
            unsigned long long ya[4], yb[4];
#pragma unroll
            for (int i = 0; i < 4; ++i) {
                float4 v = *(const float4*)(h1r[i] + 4 * kp);
                ya[i] = pack2(v.x, v.y);
                yb[i] = pack2(v.z, v.w);
            }
#pragma unroll
            for (int m = 0; m < 4; ++m) {
                uint2 w = *(const uint2*)(w2p[m] + 2 * kp);
                unsigned long long wa = bf2f2(w.x);
                unsigned long long wb = bf2f2(w.y);
#pragma unroll
                for (int i = 0; i < 4; ++i) {
                    ffma2(acc2[i][m], wa, ya[i]);
                    ffma2(acc2[i][m], wb, yb[i]);
                }
            }
        }
#pragma unroll 4
        for (int kp = 0; kp < 16; ++kp) {   // real head, k = 4*kp over h1 cols 128..191
            unsigned long long ya[4], yb[4];
#pragma unroll
            for (int i = 0; i < 4; ++i) {
                float4 v = *(const float4*)(h1r[i] + 128 + 4 * kp);
                ya[i] = pack2(v.x, v.y);
                yb[i] = pack2(v.z, v.w);
            }
#pragma unroll
            for (int m = 0; m < 2; ++m) {
                uint2 w = *(const uint2*)(wrp[m] + 2 * kp);
                unsigned long long wa = bf2f2(w.x);
                unsigned long long wb = bf2f2(w.y);
#pragma unroll
                for (int i = 0; i < 4; ++i) {
                    ffma2(acc2[i][4 + m], wa, ya[i]);
                    ffma2(acc2[i][4 + m], wb, yb[i]);
                }
            }
        }
#pragma unroll
        for (int m = 0; m < 6; ++m) {
            int f = tx + 32 * m;
            float bb = b2[f];
#pragma unroll
            for (int i = 0; i < 4; ++i)
                h2r[i][f] = hsum2(acc2[i][m]) + bb;
        }
        __syncthreads();

        // ===== Elementwise: rotate/scale complex pairs, scale reals; write y and out =====
#pragma unroll
        for (int i = 0; i < 4; ++i) {
            float* orow = out + ((size_t)(rowg0 + row0 + i) * 64 + t) * 192;
#pragma unroll
            for (int m = 0; m < 2; ++m) {
                int j2 = 2 * (tx + 32 * m);   // even feature of com pair
                float2 mo = *(const float2*)(h2r[i] + j2);   // (mu, omega)
                float2 yc = *(const float2*)(yr[i] + j2);    // (ye, yo)
                float e = __expf(0.01f * mo.x);
                float s, c;
                __sincosf(0.01f * mo.y, &s, &c);
                float2 nv;
                nv.x = e * (c * yc.x - s * yc.y);
                nv.y = e * (s * yc.x + c * yc.y);
                *(float2*)(yr[i] + j2) = nv;
                *(float2*)(orow + j2) = nv;
            }
#pragma unroll
            for (int m = 0; m < 2; ++m) {
                int f = 128 + tx + 32 * m;
                float nv = yr[i][f] * __expf(0.01f * h2r[i][f]);
                yr[i][f] = nv;
                orow[f] = nv;
            }
        }
        __syncthreads();
    }
}

extern "C" void kernel_launch(void* const* d_in, const int* in_sizes, int n_in,
                              void* d_out, int out_size)
{
    (void)in_sizes; (void)n_in; (void)out_size;
    cudaFuncSetAttribute(koopman_kernel,
                         cudaFuncAttributeMaxDynamicSharedMemorySize, SMEM_BYTES);
    koopman_kernel<<<128, 256, SMEM_BYTES>>>(
        (const float*)d_in[0],
        (const float*)d_in[1], (const float*)d_in[2],
        (const float*)d_in[3], (const float*)d_in[4],
        (const float*)d_in[5], (const float*)d_in[6],
        (const float*)d_in[7], (const float*)d_in[8],
        (float*)d_out);
}

// round 6
// speedup vs baseline: 1.0491x; 1.0456x over previous
#include <cuda_runtime.h>
#include <cuda_bf16.h>
#include <cstdint>

// Koopman rollout: B=4096, T=64, K=192 (128 complex + 64 real), DT=0.01
// Persistent CTA: 128 CTAs x 32 rows. Rows are WARP-LOCAL (warp ty owns rows
// 4*ty..4*ty+3) -> no __syncthreads in the time loop, only __syncwarp.
// W1 in SMEM as bf16x2 (converted per use); W2 in SMEM as f32 pairs (u64),
// so Phase B has zero conversion ALU. fp32 accum via fma.rn.f32x2.

#define SMEM_BYTES 213504

// byte offsets in dynamic smem
#define OFF_W1   0        // u32 [192][98]  (bf16x2 pairs along k; rows: cW1 0..127, rW1 128..191)
#define OFF_W2C  75264    // u64 [128][67]  (f32 pairs along k)
#define OFF_W2R  143872   // u64 [64][35]   (f32 pairs along k)
#define OFF_B1   161792   // f32 [192]
#define OFF_B2   162560   // f32 [192]
#define OFF_Y    163328   // f32 [32][196]
#define OFF_H    188416   // f32 [32][196]  (h1, aliased as h2)

__device__ __forceinline__ unsigned long long bf2f2(unsigned w) {
    // bf16x2 (lo = even k, hi = odd k) -> packed f32x2
    unsigned lo = w << 16;
    unsigned hi = w & 0xFFFF0000u;
    unsigned long long r;
    asm("mov.b64 %0, {%1, %2};" : "=l"(r) : "r"(lo), "r"(hi));
    return r;
}
__device__ __forceinline__ void ffma2(unsigned long long& d, unsigned long long a,
                                      unsigned long long b) {
    asm("fma.rn.f32x2 %0, %1, %2, %0;" : "+l"(d) : "l"(a), "l"(b));
}
__device__ __forceinline__ float hsum2(unsigned long long v) {
    float a, b;
    asm("mov.b64 {%0, %1}, %2;" : "=f"(a), "=f"(b) : "l"(v));
    return a + b;
}

__global__ void __launch_bounds__(256, 1)
koopman_kernel(const float* __restrict__ x,
               const float* __restrict__ cW1, const float* __restrict__ cb1,
               const float* __restrict__ cW2, const float* __restrict__ cb2,
               const float* __restrict__ rW1, const float* __restrict__ rb1,
               const float* __restrict__ rW2, const float* __restrict__ rb2,
               float* __restrict__ out)
{
    extern __shared__ unsigned char smem[];
    unsigned*            w1  = (unsigned*)(smem + OFF_W1);
    unsigned long long*  w2c = (unsigned long long*)(smem + OFF_W2C);
    unsigned long long*  w2r = (unsigned long long*)(smem + OFF_W2R);
    float* b1  = (float*)(smem + OFF_B1);
    float* b2  = (float*)(smem + OFF_B2);
    float* ysm = (float*)(smem + OFF_Y);
    float* hsm = (float*)(smem + OFF_H);

    const int tid = threadIdx.x;
    const int tx = tid & 31;
    const int ty = tid >> 5;        // warp id 0..7
    const int row0 = ty * 4;        // 4 rows per thread, warp-local
    const int rowg0 = blockIdx.x * 32;

    // ---- one-time init ----
    // W1 (bf16x2, stride 98 u32 -> conflict-free LDS.64)
    for (int idx = tid; idx < 192 * 96; idx += 256) {
        int j = idx / 96, p = idx - j * 96;
        const float* s = (j < 128) ? (cW1 + j * 192 + 2 * p)
                                   : (rW1 + (j - 128) * 192 + 2 * p);
        unsigned lo = __bfloat16_as_ushort(__float2bfloat16_rn(s[0]));
        unsigned hi = __bfloat16_as_ushort(__float2bfloat16_rn(s[1]));
        w1[j * 98 + p] = lo | (hi << 16);
    }
    // W2 complex (f32 pairs, stride 67 u64 -> word stride 134 == 6 mod 32, conflict-free)
    for (int idx = tid; idx < 128 * 64; idx += 256) {
        int j = idx >> 6, p = idx & 63;
        float2 v = make_float2(cW2[j * 128 + 2 * p], cW2[j * 128 + 2 * p + 1]);
        *(float2*)(w2c + j * 67 + p) = v;
    }
    // W2 real (f32 pairs, stride 35 u64)
    for (int idx = tid; idx < 64 * 32; idx += 256) {
        int j = idx >> 5, p = idx & 31;
        float2 v = make_float2(rW2[j * 64 + 2 * p], rW2[j * 64 + 2 * p + 1]);
        *(float2*)(w2r + j * 35 + p) = v;
    }
    if (tid < 192) {
        b1[tid] = (tid < 128) ? cb1[tid] : rb1[tid - 128];
        b2[tid] = (tid < 128) ? cb2[tid] : rb2[tid - 128];
    }
    // initial state y = x[:, 0, :]  (row stride 196 floats = 784B, 16B aligned)
    for (int idx = tid; idx < 32 * 192; idx += 256) {
        int r = idx / 192, k = idx - r * 192;
        ysm[r * 196 + k] = x[(size_t)(rowg0 + r) * (64 * 192) + k];
    }
    __syncthreads();   // only cross-warp sync in the kernel

    // per-thread constant pointers
    const unsigned* w1p[6];
    const unsigned long long* w2p[4];
    const unsigned long long* wrp[2];
#pragma unroll
    for (int m = 0; m < 6; ++m) w1p[m] = w1 + (tx + 32 * m) * 98;
#pragma unroll
    for (int m = 0; m < 4; ++m) w2p[m] = w2c + (tx + 32 * m) * 67;
#pragma unroll
    for (int m = 0; m < 2; ++m) wrp[m] = w2r + (tx + 32 * m) * 35;
    float* yr[4];
    float* hr[4];
#pragma unroll
    for (int i = 0; i < 4; ++i) {
        yr[i] = ysm + (row0 + i) * 196;
        hr[i] = hsm + (row0 + i) * 196;
    }

    for (int t = 0; t < 64; ++t) {
        // ===== Phase A: h1 = relu(y @ W1cat^T + b1cat)  (192 outs, K=192) =====
        unsigned long long acc[4][6];
#pragma unroll
        for (int i = 0; i < 4; ++i)
#pragma unroll
            for (int m = 0; m < 6; ++m) acc[i][m] = 0ull;

#pragma unroll 4
        for (int kp = 0; kp < 48; ++kp) {   // k = 4*kp .. 4*kp+3
            unsigned long long ya[4], yb[4];
#pragma unroll
            for (int i = 0; i < 4; ++i) {
                ulonglong2 v = *(const ulonglong2*)(yr[i] + 4 * kp);
                ya[i] = v.x; yb[i] = v.y;
            }
#pragma unroll
            for (int m = 0; m < 6; ++m) {
                uint2 w = *(const uint2*)(w1p[m] + 2 * kp);
                unsigned long long wa = bf2f2(w.x);
                unsigned long long wb = bf2f2(w.y);
#pragma unroll
                for (int i = 0; i < 4; ++i) {
                    ffma2(acc[i][m], wa, ya[i]);
                    ffma2(acc[i][m], wb, yb[i]);
                }
            }
        }
#pragma unroll
        for (int m = 0; m < 6; ++m) {
            int f = tx + 32 * m;
            float bb = b1[f];
#pragma unroll
            for (int i = 0; i < 4; ++i)
                hr[i][f] = fmaxf(hsum2(acc[i][m]) + bb, 0.0f);
        }
        __syncwarp();

        // ===== Phase B: h2 = h1[:, :128] @ cW2^T ; r2 = h1[:,128:] @ rW2^T (f32 weights) =====
        unsigned long long acc2[4][6];
#pragma unroll
        for (int i = 0; i < 4; ++i)
#pragma unroll
            for (int m = 0; m < 6; ++m) acc2[i][m] = 0ull;

#pragma unroll 4
        for (int kp = 0; kp < 32; ++kp) {   // complex head
            unsigned long long ya[4], yb[4];
#pragma unroll
            for (int i = 0; i < 4; ++i) {
                ulonglong2 v = *(const ulonglong2*)(hr[i] + 4 * kp);
                ya[i] = v.x; yb[i] = v.y;
            }
#pragma unroll
            for (int m = 0; m < 4; ++m) {
                unsigned long long wa = w2p[m][2 * kp];
                unsigned long long wb = w2p[m][2 * kp + 1];
#pragma unroll
                for (int i = 0; i < 4; ++i) {
                    ffma2(acc2[i][m], wa, ya[i]);
                    ffma2(acc2[i][m], wb, yb[i]);
                }
            }
        }
#pragma unroll 4
        for (int kp = 0; kp < 16; ++kp) {   // real head (h1 cols 128..191)
            unsigned long long ya[4], yb[4];
#pragma unroll
            for (int i = 0; i < 4; ++i) {
                ulonglong2 v = *(const ulonglong2*)(hr[i] + 128 + 4 * kp);
                ya[i] = v.x; yb[i] = v.y;
            }
#pragma unroll
            for (int m = 0; m < 2; ++m) {
                unsigned long long wa = wrp[m][2 * kp];
                unsigned long long wb = wrp[m][2 * kp + 1];
#pragma unroll
                for (int i = 0; i < 4; ++i) {
                    ffma2(acc2[i][4 + m], wa, ya[i]);
                    ffma2(acc2[i][4 + m], wb, yb[i]);
                }
            }
        }
        __syncwarp();   // all h1 reads done before overwriting buffer with h2
#pragma unroll
        for (int m = 0; m < 6; ++m) {
            int f = tx + 32 * m;
            float bb = b2[f];
#pragma unroll
            for (int i = 0; i < 4; ++i)
                hr[i][f] = hsum2(acc2[i][m]) + bb;   // h2 aliases h1 buffer
        }
        __syncwarp();

        // ===== Elementwise: rotate/scale complex pairs, scale reals; write y and out =====
#pragma unroll
        for (int i = 0; i < 4; ++i) {
            float* orow = out + ((size_t)(rowg0 + row0 + i) * 64 + t) * 192;
#pragma unroll
            for (int m = 0; m < 2; ++m) {
                int j2 = 2 * (tx + 32 * m);   // even feature of complex pair
                float2 mo = *(const float2*)(hr[i] + j2);   // (mu, omega)
                float2 yc = *(const float2*)(yr[i] + j2);   // (ye, yo)
                float e = __expf(0.01f * mo.x);
                float s, c;
                __sincosf(0.01f * mo.y, &s, &c);
                float2 nv;
                nv.x = e * (c * yc.x - s * yc.y);
                nv.y = e * (s * yc.x + c * yc.y);
                *(float2*)(yr[i] + j2) = nv;
                *(float2*)(orow + j2) = nv;
            }
#pragma unroll
            for (int m = 0; m < 2; ++m) {
                int f = 128 + tx + 32 * m;
                float nv = yr[i][f] * __expf(0.01f * hr[i][f]);
                yr[i][f] = nv;
                orow[f] = nv;
            }
        }
        __syncwarp();   // y writes visible to whole warp before next Phase A
    }
}

extern "C" void kernel_launch(void* const* d_in, const int* in_sizes, int n_in,
                              void* d_out, int out_size)
{
    (void)in_sizes; (void)n_in; (void)out_size;
    cudaFuncSetAttribute(koopman_kernel,
                         cudaFuncAttributeMaxDynamicSharedMemorySize, SMEM_BYTES);
    koopman_kernel<<<128, 256, SMEM_BYTES>>>(
        (const float*)d_in[0],
        (const float*)d_in[1], (const float*)d_in[2],
        (const float*)d_in[3], (const float*)d_in[4],
        (const float*)d_in[5], (const float*)d_in[6],
        (const float*)d_in[7], (const float*)d_in[8],
        (float*)d_out);
}

// round 8
// speedup vs baseline: 3.2932x; 3.1390x over previous
#include <cuda_runtime.h>
#include <cuda_bf16.h>
#include <cstdint>

// Koopman rollout via warp-level HMMA (mma.sync.m16n8k16.bf16), sm_103-safe PTX.
// 128 CTAs x 2 warps; each warp owns 16 batch rows and the full 192-feature dim.
// All activations (y fp32 master, h1 bf16 fragments) live in registers; the
// m16n8k16 C-fragment layout == A-fragment layout, so MMA outputs feed the next
// MMA's A operand with just a cvt. Weights bf16 in SMEM (padded, ldmatrix-ready).
// No synchronization inside the 64-step time loop.

#define SMEM_BYTES 122368u
#define OFF_W1  0u        // [192 n][k stride 200 bf16 = 400B]  76800 B
#define OFF_W2C 76800u    // [128 n][k stride 136 bf16 = 272B]  34816 B
#define OFF_W2R 111616u   // [64 n][k stride 72 bf16 = 144B]     9216 B
#define OFF_B1  120832u   // f32[192]
#define OFF_B2  121600u   // f32[192]

__device__ __forceinline__ unsigned smem_u32(const void* p) {
    unsigned a;
    asm("{ .reg .u64 t; cvta.to.shared.u64 t, %1; cvt.u32.u64 %0, t; }"
        : "=r"(a) : "l"(p));
    return a;
}
// pack two f32 -> bf16x2 (lo = first arg)
__device__ __forceinline__ unsigned pbf(float lo, float hi) {
    unsigned r;
    asm("cvt.rn.bf16x2.f32 %0, %1, %2;" : "=r"(r) : "f"(hi), "f"(lo));
    return r;
}

#define LDSM4(r0, r1, r2, r3, a) \
    asm volatile("ldmatrix.sync.aligned.m8n8.x4.shared.b16 {%0,%1,%2,%3}, [%4];" \
                 : "=r"(r0), "=r"(r1), "=r"(r2), "=r"(r3) : "r"(a))

#define MMA(d, a0, a1, a2, a3, b0, b1) \
    asm volatile("mma.sync.aligned.m16n8k16.row.col.f32.bf16.bf16.f32 " \
                 "{%0,%1,%2,%3},{%4,%5,%6,%7},{%8,%9},{%0,%1,%2,%3};" \
                 : "+f"((d)[0]), "+f"((d)[1]), "+f"((d)[2]), "+f"((d)[3]) \
                 : "r"(a0), "r"(a1), "r"(a2), "r"(a3), "r"(b0), "r"(b1))

__global__ void __launch_bounds__(64, 1)
koopman_mma_kernel(const float* __restrict__ x,
                   const float* __restrict__ cW1, const float* __restrict__ cb1,
                   const float* __restrict__ cW2, const float* __restrict__ cb2,
                   const float* __restrict__ rW1, const float* __restrict__ rb1,
                   const float* __restrict__ rW2, const float* __restrict__ rb2,
                   float* __restrict__ out)
{
    extern __shared__ unsigned char smem[];
    const unsigned sb = smem_u32(smem);
    const int tid = threadIdx.x;
    const int lane = tid & 31;
    const int w = tid >> 5;            // warp 0..1

    float* b1f = (float*)(smem + OFF_B1);
    float* b2f = (float*)(smem + OFF_B2);

    // ---- one-time: weights -> bf16 SMEM (k-strides padded to 16 mod 128 B) ----
    for (int idx = tid; idx < 192 * 96; idx += 64) {
        int n = idx / 96, k = 2 * (idx - n * 96);
        const float* s = (n < 128) ? (cW1 + n * 192 + k) : (rW1 + (n - 128) * 192 + k);
        *(unsigned*)(smem + OFF_W1 + n * 400 + k * 2) = pbf(s[0], s[1]);
    }
    for (int idx = tid; idx < 128 * 64; idx += 64) {
        int n = idx >> 6, k = 2 * (idx & 63);
        *(unsigned*)(smem + OFF_W2C + n * 272 + k * 2) =
            pbf(cW2[n * 128 + k], cW2[n * 128 + k + 1]);
    }
    for (int idx = tid; idx < 64 * 32; idx += 64) {
        int n = idx >> 5, k = 2 * (idx & 31);
        *(unsigned*)(smem + OFF_W2R + n * 144 + k * 2) =
            pbf(rW2[n * 64 + k], rW2[n * 64 + k + 1]);
    }
    for (int i = tid; i < 192; i += 64) {
        b1f[i] = (i < 128) ? cb1[i] : rb1[i - 128];
        b2f[i] = (i < 128) ? cb2[i] : rb2[i - 128];
    }
    __syncthreads();   // only barrier in the kernel

    // ---- per-lane constants ----
    const int colb = 2 * (lane & 3);             // col offset within an 8-wide n-tile
    const int r0g = blockIdx.x * 32 + w * 16 + (lane >> 2);
    const int r1g = r0g + 8;
    // ldmatrix lane base: matrices m0,m1 = n-rows 0..7 (k-blocks 0,8); m2,m3 = n-rows 8..15
    const int lrow = (lane & 7) + ((lane >> 4) << 3);
    const unsigned lkb = ((lane >> 3) & 1) * 16;
    const unsigned bW1  = sb + OFF_W1  + lrow * 400 + lkb;
    const unsigned bW2C = sb + OFF_W2C + lrow * 272 + lkb;
    const unsigned bW2R = sb + OFF_W2R + lrow * 144 + lkb;

    // ---- y state in registers: y[j] = state cols 8j+colb+{0,1}, rows r0g / r1g ----
    float y[24][4];
    {
        const float* x0 = x + (size_t)r0g * 12288;   // x[:,0,:], row stride 64*192
        const float* x1 = x + (size_t)r1g * 12288;
#pragma unroll
        for (int j = 0; j < 24; ++j) {
            int col = 8 * j + colb;
            float2 v0 = *(const float2*)(x0 + col);
            float2 v1 = *(const float2*)(x1 + col);
            y[j][0] = v0.x; y[j][1] = v0.y;
            y[j][2] = v1.x; y[j][3] = v1.y;
        }
    }

    unsigned h1lo[24], h1hi[24];

#pragma unroll 1
    for (int t = 0; t < 64; ++t) {
        // ===== MMA1: h1 = relu(y @ W1cat^T + b1), N=192 in 4 quarters of 6 n-tiles =====
#pragma unroll
        for (int q = 0; q < 4; ++q) {
            float acc[6][4];
#pragma unroll
            for (int n = 0; n < 6; ++n)
#pragma unroll
                for (int e = 0; e < 4; ++e) acc[n][e] = 0.0f;
#pragma unroll
            for (int k = 0; k < 12; ++k) {
                unsigned a0 = pbf(y[2 * k][0],     y[2 * k][1]);
                unsigned a1 = pbf(y[2 * k][2],     y[2 * k][3]);
                unsigned a2 = pbf(y[2 * k + 1][0], y[2 * k + 1][1]);
                unsigned a3 = pbf(y[2 * k + 1][2], y[2 * k + 1][3]);
#pragma unroll
                for (int p = 0; p < 3; ++p) {
                    unsigned b0, b1r, b2r, b3r;
                    LDSM4(b0, b1r, b2r, b3r, bW1 + (3 * q + p) * 6400 + k * 32);
                    MMA(acc[2 * p],     a0, a1, a2, a3, b0, b1r);
                    MMA(acc[2 * p + 1], a0, a1, a2, a3, b2r, b3r);
                }
            }
#pragma unroll
            for (int n = 0; n < 6; ++n) {
                int gn = 6 * q + n;
                float2 bb = *(const float2*)(b1f + 8 * gn + colb);
                h1lo[gn] = pbf(fmaxf(acc[n][0] + bb.x, 0.0f),
                               fmaxf(acc[n][1] + bb.y, 0.0f));
                h1hi[gn] = pbf(fmaxf(acc[n][2] + bb.x, 0.0f),
                               fmaxf(acc[n][3] + bb.y, 0.0f));
            }
        }

        float* o0 = out + ((size_t)r0g * 64 + t) * 192;
        float* o1 = out + ((size_t)r1g * 64 + t) * 192;

        // ===== MMA2 complex: h2[:, :128] = h1[:, :128] @ cW2^T + cb2; rotate state =====
#pragma unroll
        for (int hh = 0; hh < 2; ++hh) {
            float acc[8][4];
#pragma unroll
            for (int n = 0; n < 8; ++n)
#pragma unroll
                for (int e = 0; e < 4; ++e) acc[n][e] = 0.0f;
#pragma unroll
            for (int k = 0; k < 8; ++k) {
                unsigned a0 = h1lo[2 * k], a1 = h1hi[2 * k];
                unsigned a2 = h1lo[2 * k + 1], a3 = h1hi[2 * k + 1];
#pragma unroll
                for (int p = 0; p < 4; ++p) {
                    unsigned b0, b1r, b2r, b3r;
                    LDSM4(b0, b1r, b2r, b3r, bW2C + (4 * hh + p) * 4352 + k * 32);
                    MMA(acc[2 * p],     a0, a1, a2, a3, b0, b1r);
                    MMA(acc[2 * p + 1], a0, a1, a2, a3, b2r, b3r);
                }
            }
#pragma unroll
            for (int n = 0; n < 8; ++n) {
                int gn = 8 * hh + n;
                int col = 8 * gn + colb;          // even col = mu, odd = omega
                float2 bb = *(const float2*)(b2f + col);
                float e0 = __expf(0.01f * (acc[n][0] + bb.x));
                float s0, c0;
                __sincosf(0.01f * (acc[n][1] + bb.y), &s0, &c0);
                float ye = y[gn][0], yo = y[gn][1];
                y[gn][0] = e0 * (c0 * ye - s0 * yo);
                y[gn][1] = e0 * (s0 * ye + c0 * yo);
                float e1 = __expf(0.01f * (acc[n][2] + bb.x));
                float s1, c1;
                __sincosf(0.01f * (acc[n][3] + bb.y), &s1, &c1);
                ye = y[gn][2]; yo = y[gn][3];
                y[gn][2] = e1 * (c1 * ye - s1 * yo);
                y[gn][3] = e1 * (s1 * ye + c1 * yo);
                *(float2*)(o0 + col) = make_float2(y[gn][0], y[gn][1]);
                *(float2*)(o1 + col) = make_float2(y[gn][2], y[gn][3]);
            }
        }

        // ===== MMA2 real: re = h1[:,128:] @ rW2^T + rb2; scale real state =====
        {
            float acc[8][4];
#pragma unroll
            for (int n = 0; n < 8; ++n)
#pragma unroll
                for (int e = 0; e < 4; ++e) acc[n][e] = 0.0f;
#pragma unroll
            for (int k = 0; k < 4; ++k) {
                unsigned a0 = h1lo[16 + 2 * k], a1 = h1hi[16 + 2 * k];
                unsigned a2 = h1lo[17 + 2 * k], a3 = h1hi[17 + 2 * k];
#pragma unroll
                for (int p = 0; p < 4; ++p) {
                    unsigned b0, b1r, b2r, b3r;
                    LDSM4(b0, b1r, b2r, b3r, bW2R + p * 2304 + k * 32);
                    MMA(acc[2 * p],     a0, a1, a2, a3, b0, b1r);
                    MMA(acc[2 * p + 1], a0, a1, a2, a3, b2r, b3r);
                }
            }
#pragma unroll
            for (int n = 0; n < 8; ++n) {
                int j = 16 + n;
                int col = 128 + 8 * n + colb;
                float2 bb = *(const float2*)(b2f + col);
                y[j][0] *= __expf(0.01f * (acc[n][0] + bb.x));
                y[j][1] *= __expf(0.01f * (acc[n][1] + bb.y));
                y[j][2] *= __expf(0.01f * (acc[n][2] + bb.x));
                y[j][3] *= __expf(0.01f * (acc[n][3] + bb.y));
                *(float2*)(o0 + col) = make_float2(y[j][0], y[j][1]);
                *(float2*)(o1 + col) = make_float2(y[j][2], y[j][3]);
            }
        }
    }
}

extern "C" void kernel_launch(void* const* d_in, const int* in_sizes, int n_in,
                              void* d_out, int out_size)
{
    (void)in_sizes; (void)n_in; (void)out_size;
    cudaFuncSetAttribute(koopman_mma_kernel,
                         cudaFuncAttributeMaxDynamicSharedMemorySize, SMEM_BYTES);
    koopman_mma_kernel<<<128, 64, SMEM_BYTES>>>(
        (const float*)d_in[0],
        (const float*)d_in[1], (const float*)d_in[2],
        (const float*)d_in[3], (const float*)d_in[4],
        (const float*)d_in[5], (const float*)d_in[6],
        (const float*)d_in[7], (const float*)d_in[8],
        (float*)d_out);
}

// round 9
// speedup vs baseline: 5.3527x; 1.6254x over previous
#include <cuda_runtime.h>
#include <cuda_bf16.h>
#include <cstdint>

// Koopman rollout via warp-level HMMA, feature-split across 8 warps/CTA.
// 128 CTAs x 8 warps; CTA owns 32 rows = 2 row-groups x 16 rows.
// Within a row-group, 4 warps each own a quarter of the feature dim:
//   MMA1 (N=192): warp q computes n-tiles 6q..6q+5          (72 MMAs)
//   MMA2c (N=128): n-tiles 4q..4q+3                          (32 MMAs)
//   MMA2r (N=64):  n-tiles 2q..2q+1                          ( 8 MMAs)
// Activation fragments (bf16) are exchanged via per-lane SMEM rows so the
// next GEMM's A-operand is one LDS.128 per k-iter. y master fp32 in regs.

#define SMEM_BYTES 148992u
#define OFF_W1  0u        // [192 n][k stride 400B bf16]   76800 B
#define OFF_W2C 76800u    // [128 n][k stride 272B]        34816 B
#define OFF_W2R 111616u   // [64 n][k stride 144B]          9216 B
#define OFF_B1  120832u   // f32[192]
#define OFF_B2  121600u   // f32[192]
#define OFF_YB  122368u   // y frags: [2 grp][32 lane][52 u32]  13312 B
#define OFF_HB  135680u   // h1 frags: same                      13312 B

__device__ __forceinline__ unsigned smem_u32(const void* p) {
    unsigned a;
    asm("{ .reg .u64 t; cvta.to.shared.u64 t, %1; cvt.u32.u64 %0, t; }"
        : "=r"(a) : "l"(p));
    return a;
}
// pack two f32 -> bf16x2 (first arg -> low half)
__device__ __forceinline__ unsigned pbf(float lo, float hi) {
    unsigned r;
    asm("cvt.rn.bf16x2.f32 %0, %1, %2;" : "=r"(r) : "f"(hi), "f"(lo));
    return r;
}

#define LDSM4(r0, r1, r2, r3, a) \
    asm volatile("ldmatrix.sync.aligned.m8n8.x4.shared.b16 {%0,%1,%2,%3}, [%4];" \
                 : "=r"(r0), "=r"(r1), "=r"(r2), "=r"(r3) : "r"(a))

#define MMA(d, a0, a1, a2, a3, b0, b1) \
    asm volatile("mma.sync.aligned.m16n8k16.row.col.f32.bf16.bf16.f32 " \
                 "{%0,%1,%2,%3},{%4,%5,%6,%7},{%8,%9},{%0,%1,%2,%3};" \
                 : "+f"((d)[0]), "+f"((d)[1]), "+f"((d)[2]), "+f"((d)[3]) \
                 : "r"(a0), "r"(a1), "r"(a2), "r"(a3), "r"(b0), "r"(b1))

__global__ void __launch_bounds__(256, 1)
koopman_mma8_kernel(const float* __restrict__ x,
                    const float* __restrict__ cW1, const float* __restrict__ cb1,
                    const float* __restrict__ cW2, const float* __restrict__ cb2,
                    const float* __restrict__ rW1, const float* __restrict__ rb1,
                    const float* __restrict__ rW2, const float* __restrict__ rb2,
                    float* __restrict__ out)
{
    extern __shared__ unsigned char smem[];
    const unsigned sb = smem_u32(smem);
    const int tid = threadIdx.x;
    const int lane = tid & 31;
    const int wid = tid >> 5;
    const int g = wid >> 2;            // row-group 0..1
    const int q = wid & 3;             // feature quarter 0..3

    float* b1f = (float*)(smem + OFF_B1);
    float* b2f = (float*)(smem + OFF_B2);

    // ---- one-time: weights -> bf16 SMEM (k-strides 16 mod 128 B: LDSM-friendly) ----
    for (int idx = tid; idx < 192 * 96; idx += 256) {
        int n = idx / 96, k = 2 * (idx - n * 96);
        const float* s = (n < 128) ? (cW1 + n * 192 + k) : (rW1 + (n - 128) * 192 + k);
        *(unsigned*)(smem + OFF_W1 + n * 400 + k * 2) = pbf(s[0], s[1]);
    }
    for (int idx = tid; idx < 128 * 64; idx += 256) {
        int n = idx >> 6, k = 2 * (idx & 63);
        *(unsigned*)(smem + OFF_W2C + n * 272 + k * 2) =
            pbf(cW2[n * 128 + k], cW2[n * 128 + k + 1]);
    }
    for (int idx = tid; idx < 64 * 32; idx += 256) {
        int n = idx >> 5, k = 2 * (idx & 31);
        *(unsigned*)(smem + OFF_W2R + n * 144 + k * 2) =
            pbf(rW2[n * 64 + k], rW2[n * 64 + k + 1]);
    }
    for (int i = tid; i < 192; i += 256) {
        b1f[i] = (i < 128) ? cb1[i] : rb1[i - 128];
        b2f[i] = (i < 128) ? cb2[i] : rb2[i - 128];
    }

    // ---- per-lane constants ----
    const int colb = 2 * (lane & 3);
    const int r0g = blockIdx.x * 32 + g * 16 + (lane >> 2);
    const int r1g = r0g + 8;
    const int lrow = (lane & 7) + ((lane >> 4) << 3);
    const unsigned lkb = ((lane >> 3) & 1) * 16;
    const unsigned bW1  = sb + OFF_W1  + lrow * 400 + lkb + q * 3 * 6400;
    const unsigned bW2C = sb + OFF_W2C + lrow * 272 + lkb + q * 2 * 4352;
    const unsigned bW2R = sb + OFF_W2R + lrow * 144 + lkb + q * 2304;

    // frag-exchange rows (52 u32 per lane; [tile*2+part])
    unsigned* yb = (unsigned*)(smem + OFF_YB) + (g * 32 + lane) * 52;
    unsigned* hb = (unsigned*)(smem + OFF_HB) + (g * 32 + lane) * 52;

    // ---- y master state: 6 owned col-tiles (4 complex, 2 real) ----
    // tile j<4: global y col-tile 4q+j; j>=4: 16+2q+(j-4). vals: [0,1]=row r0 cols (c,c+1); [2,3]=row r1
    float ym[6][4];
    int gtile[6];
#pragma unroll
    for (int j = 0; j < 6; ++j) gtile[j] = (j < 4) ? (4 * q + j) : (16 + 2 * q + j - 4);
    {
        const float* x0 = x + (size_t)r0g * 12288;
        const float* x1 = x + (size_t)r1g * 12288;
#pragma unroll
        for (int j = 0; j < 6; ++j) {
            int col = 8 * gtile[j] + colb;
            float2 v0 = *(const float2*)(x0 + col);
            float2 v1 = *(const float2*)(x1 + col);
            ym[j][0] = v0.x; ym[j][1] = v0.y; ym[j][2] = v1.x; ym[j][3] = v1.y;
        }
        // publish initial y fragments
#pragma unroll
        for (int j = 0; j < 6; ++j) {
            uint2 f;
            f.x = pbf(ym[j][0], ym[j][1]);
            f.y = pbf(ym[j][2], ym[j][3]);
            *(uint2*)(yb + 2 * gtile[j]) = f;
        }
    }
    __syncthreads();

#pragma unroll 1
    for (int t = 0; t < 64; ++t) {
        // ===== MMA1: warp computes h1 n-tiles 6q..6q+5 over K=192 =====
        float acc[6][4];
#pragma unroll
        for (int n = 0; n < 6; ++n)
#pragma unroll
            for (int e = 0; e < 4; ++e) acc[n][e] = 0.0f;
#pragma unroll
        for (int k = 0; k < 12; ++k) {
            uint4 av = *(const uint4*)(yb + 4 * k);   // a0,a1,a2,a3
#pragma unroll
            for (int p = 0; p < 3; ++p) {
                unsigned b0, b1r, b2r, b3r;
                LDSM4(b0, b1r, b2r, b3r, bW1 + p * 6400 + k * 32);
                MMA(acc[2 * p],     av.x, av.y, av.z, av.w, b0, b1r);
                MMA(acc[2 * p + 1], av.x, av.y, av.z, av.w, b2r, b3r);
            }
        }
        // h1 = relu(. + b1) -> bf16 frags -> exchange
#pragma unroll
        for (int n = 0; n < 6; ++n) {
            int gn = 6 * q + n;
            float2 bb = *(const float2*)(b1f + 8 * gn + colb);
            uint2 f;
            f.x = pbf(fmaxf(acc[n][0] + bb.x, 0.0f), fmaxf(acc[n][1] + bb.y, 0.0f));
            f.y = pbf(fmaxf(acc[n][2] + bb.x, 0.0f), fmaxf(acc[n][3] + bb.y, 0.0f));
            *(uint2*)(hb + 2 * gn) = f;
        }
        __syncthreads();

        // ===== MMA2: complex n-tiles 4q..4q+3 (K=128) + real n-tiles 2q..2q+1 (K=64) =====
        float ac[4][4], ar[2][4];
#pragma unroll
        for (int n = 0; n < 4; ++n)
#pragma unroll
            for (int e = 0; e < 4; ++e) ac[n][e] = 0.0f;
#pragma unroll
        for (int n = 0; n < 2; ++n)
#pragma unroll
            for (int e = 0; e < 4; ++e) ar[n][e] = 0.0f;

#pragma unroll
        for (int k = 0; k < 8; ++k) {
            uint4 av = *(const uint4*)(hb + 4 * k);
#pragma unroll
            for (int p = 0; p < 2; ++p) {
                unsigned b0, b1r, b2r, b3r;
                LDSM4(b0, b1r, b2r, b3r, bW2C + p * 4352 + k * 32);
                MMA(ac[2 * p],     av.x, av.y, av.z, av.w, b0, b1r);
                MMA(ac[2 * p + 1], av.x, av.y, av.z, av.w, b2r, b3r);
            }
        }
#pragma unroll
        for (int k = 0; k < 4; ++k) {
            uint4 av = *(const uint4*)(hb + 32 + 4 * k);
            unsigned b0, b1r, b2r, b3r;
            LDSM4(b0, b1r, b2r, b3r, bW2R + k * 32);
            MMA(ar[0], av.x, av.y, av.z, av.w, b0, b1r);
            MMA(ar[1], av.x, av.y, av.z, av.w, b2r, b3r);
        }

        // ===== epilogue: state update + out + publish new y frags =====
        float* o0 = out + ((size_t)r0g * 64 + t) * 192;
        float* o1 = out + ((size_t)r1g * 64 + t) * 192;
#pragma unroll
        for (int n = 0; n < 4; ++n) {     // complex: even col = mu, odd = omega
            int col = 8 * gtile[n] + colb;
            float2 bb = *(const float2*)(b2f + col);
            float e0 = __expf(0.01f * (ac[n][0] + bb.x));
            float s0, c0;
            __sincosf(0.01f * (ac[n][1] + bb.y), &s0, &c0);
            float ye = ym[n][0], yo = ym[n][1];
            ym[n][0] = e0 * (c0 * ye - s0 * yo);
            ym[n][1] = e0 * (s0 * ye + c0 * yo);
            float e1 = __expf(0.01f * (ac[n][2] + bb.x));
            float s1, c1;
            __sincosf(0.01f * (ac[n][3] + bb.y), &s1, &c1);
            ye = ym[n][2]; yo = ym[n][3];
            ym[n][2] = e1 * (c1 * ye - s1 * yo);
            ym[n][3] = e1 * (s1 * ye + c1 * yo);
            *(float2*)(o0 + col) = make_float2(ym[n][0], ym[n][1]);
            *(float2*)(o1 + col) = make_float2(ym[n][2], ym[n][3]);
        }
#pragma unroll
        for (int j = 4; j < 6; ++j) {     // real diagonal
            int n = j - 4;
            int col = 8 * gtile[j] + colb;
            float2 bb = *(const float2*)(b2f + col);
            ym[j][0] *= __expf(0.01f * (ar[n][0] + bb.x));
            ym[j][1] *= __expf(0.01f * (ar[n][1] + bb.y));
            ym[j][2] *= __expf(0.01f * (ar[n][2] + bb.x));
            ym[j][3] *= __expf(0.01f * (ar[n][3] + bb.y));
            *(float2*)(o0 + col) = make_float2(ym[j][0], ym[j][1]);
            *(float2*)(o1 + col) = make_float2(ym[j][2], ym[j][3]);
        }
#pragma unroll
        for (int j = 0; j < 6; ++j) {
            uint2 f;
            f.x = pbf(ym[j][0], ym[j][1]);
            f.y = pbf(ym[j][2], ym[j][3]);
            *(uint2*)(yb + 2 * gtile[j]) = f;
        }
        __syncthreads();
    }
}

extern "C" void kernel_launch(void* const* d_in, const int* in_sizes, int n_in,
                              void* d_out, int out_size)
{
    (void)in_sizes; (void)n_in; (void)out_size;
    cudaFuncSetAttribute(koopman_mma8_kernel,
                         cudaFuncAttributeMaxDynamicSharedMemorySize, SMEM_BYTES);
    koopman_mma8_kernel<<<128, 256, SMEM_BYTES>>>(
        (const float*)d_in[0],
        (const float*)d_in[1], (const float*)d_in[2],
        (const float*)d_in[3], (const float*)d_in[4],
        (const float*)d_in[5], (const float*)d_in[6],
        (const float*)d_in[7], (const float*)d_in[8],
        (float*)d_out);
}

// round 10
// speedup vs baseline: 6.6415x; 1.2408x over previous
#include <cuda_runtime.h>
#include <cuda_bf16.h>
#include <cstdint>

// Koopman rollout via warp-level HMMA with WEIGHTS RESIDENT IN REGISTERS.
// 128 CTAs x 8 warps; CTA owns 32 rows (2 row-groups x 16). Each warp owns an
// EIGHTH of the feature dim but covers BOTH row-groups, so its B-fragments
// (112 regs) are loaded by ldmatrix ONCE and reused for all 64 steps:
//   MMA1 (N=192): warp e owns n-tiles 3e..3e+2   -> 72 MMA/step
//   MMA2c (N=128): n-tiles 2e..2e+1              -> 32 MMA/step
//   MMA2r (N=64):  n-tile  e                     ->  8 MMA/step
// Inner loop has NO ldmatrix and NO weight SMEM reads; only activation
// fragment exchange (bf16, per-lane rows, LDS.128) + 2 barriers per step.
// y master state fp32 in registers.

#define SMEM_BYTES 148992u
#define OFF_W1  0u        // [192 n][k stride 400B bf16]   76800 B (init only)
#define OFF_W2C 76800u    // [128 n][k stride 272B]        34816 B (init only)
#define OFF_W2R 111616u   // [64 n][k stride 144B]          9216 B (init only)
#define OFF_B1  120832u   // f32[192]
#define OFF_B2  121600u   // f32[192]
#define OFF_YB  122368u   // y frags: [2 grp][32 lane][52 u32]  13312 B
#define OFF_HB  135680u   // h1 frags: same                      13312 B

__device__ __forceinline__ unsigned smem_u32(const void* p) {
    unsigned a;
    asm("{ .reg .u64 t; cvta.to.shared.u64 t, %1; cvt.u32.u64 %0, t; }"
        : "=r"(a) : "l"(p));
    return a;
}
// pack two f32 -> bf16x2 (first arg -> low half)
__device__ __forceinline__ unsigned pbf(float lo, float hi) {
    unsigned r;
    asm("cvt.rn.bf16x2.f32 %0, %1, %2;" : "=r"(r) : "f"(hi), "f"(lo));
    return r;
}

#define LDSM4(r0, r1, r2, r3, a) \
    asm volatile("ldmatrix.sync.aligned.m8n8.x4.shared.b16 {%0,%1,%2,%3}, [%4];" \
                 : "=r"(r0), "=r"(r1), "=r"(r2), "=r"(r3) : "r"(a))
#define LDSM2(r0, r1, a) \
    asm volatile("ldmatrix.sync.aligned.m8n8.x2.shared.b16 {%0,%1}, [%2];" \
                 : "=r"(r0), "=r"(r1) : "r"(a))

#define MMA(d, a0, a1, a2, a3, b0, b1) \
    asm volatile("mma.sync.aligned.m16n8k16.row.col.f32.bf16.bf16.f32 " \
                 "{%0,%1,%2,%3},{%4,%5,%6,%7},{%8,%9},{%0,%1,%2,%3};" \
                 : "+f"((d)[0]), "+f"((d)[1]), "+f"((d)[2]), "+f"((d)[3]) \
                 : "r"(a0), "r"(a1), "r"(a2), "r"(a3), "r"(b0), "r"(b1))

__global__ void __launch_bounds__(256, 1)
koopman_rw_kernel(const float* __restrict__ x,
                  const float* __restrict__ cW1, const float* __restrict__ cb1,
                  const float* __restrict__ cW2, const float* __restrict__ cb2,
                  const float* __restrict__ rW1, const float* __restrict__ rb1,
                  const float* __restrict__ rW2, const float* __restrict__ rb2,
                  float* __restrict__ out)
{
    extern __shared__ unsigned char smem[];
    const unsigned sb = smem_u32(smem);
    const int tid = threadIdx.x;
    const int lane = tid & 31;
    const int e = tid >> 5;            // feature eighth 0..7

    float* b1f = (float*)(smem + OFF_B1);
    float* b2f = (float*)(smem + OFF_B2);

    // ---- one-time: weights -> bf16 SMEM (staging for ldmatrix) ----
    for (int idx = tid; idx < 192 * 96; idx += 256) {
        int n = idx / 96, k = 2 * (idx - n * 96);
        const float* s = (n < 128) ? (cW1 + n * 192 + k) : (rW1 + (n - 128) * 192 + k);
        *(unsigned*)(smem + OFF_W1 + n * 400 + k * 2) = pbf(s[0], s[1]);
    }
    for (int idx = tid; idx < 128 * 64; idx += 256) {
        int n = idx >> 6, k = 2 * (idx & 63);
        *(unsigned*)(smem + OFF_W2C + n * 272 + k * 2) =
            pbf(cW2[n * 128 + k], cW2[n * 128 + k + 1]);
    }
    for (int idx = tid; idx < 64 * 32; idx += 256) {
        int n = idx >> 5, k = 2 * (idx & 31);
        *(unsigned*)(smem + OFF_W2R + n * 144 + k * 2) =
            pbf(rW2[n * 64 + k], rW2[n * 64 + k + 1]);
    }
    for (int i = tid; i < 192; i += 256) {
        b1f[i] = (i < 128) ? cb1[i] : rb1[i - 128];
        b2f[i] = (i < 128) ? cb2[i] : rb2[i - 128];
    }
    __syncthreads();

    // ---- per-lane constants ----
    const int colb = 2 * (lane & 3);
    const int lrow = (lane & 7) + ((lane >> 4) << 3);
    const unsigned lkb = ((lane >> 3) & 1) * 16;

    // ---- load persistent B-fragments (weights) into registers ----
    unsigned B1[12][3][2], B2c[8][2][2], B2r[4][2];
    {
        const unsigned aW1  = sb + OFF_W1 + e * 9600 + lrow * 400 + lkb;          // rows 24e..24e+15
        const unsigned aW1t = sb + OFF_W1 + e * 9600 + 6400 + (lane & 7) * 400 + lkb; // rows 24e+16..23
        const unsigned aW2C = sb + OFF_W2C + e * 4352 + lrow * 272 + lkb;         // rows 16e..16e+15
        const unsigned aW2R = sb + OFF_W2R + e * 1152 + (lane & 7) * 144 + lkb;   // rows 8e..8e+7
#pragma unroll
        for (int k = 0; k < 12; ++k) {
            LDSM4(B1[k][0][0], B1[k][0][1], B1[k][1][0], B1[k][1][1], aW1 + k * 32);
            LDSM2(B1[k][2][0], B1[k][2][1], aW1t + k * 32);
        }
#pragma unroll
        for (int k = 0; k < 8; ++k)
            LDSM4(B2c[k][0][0], B2c[k][0][1], B2c[k][1][0], B2c[k][1][1], aW2C + k * 32);
#pragma unroll
        for (int k = 0; k < 4; ++k)
            LDSM2(B2r[k][0], B2r[k][1], aW2R + k * 32);
    }

    // ---- bias registers for owned columns ----
    float2 bc1[3], bc2[2], br2;
#pragma unroll
    for (int n = 0; n < 3; ++n) bc1[n] = *(const float2*)(b1f + 8 * (3 * e + n) + colb);
#pragma unroll
    for (int n = 0; n < 2; ++n) bc2[n] = *(const float2*)(b2f + 8 * (2 * e + n) + colb);
    br2 = *(const float2*)(b2f + 128 + 8 * e + colb);

    // ---- frag exchange rows (52-u32 lane stride: conflict-free LDS.128) ----
    unsigned* ybg[2];
    unsigned* hbg[2];
#pragma unroll
    for (int g = 0; g < 2; ++g) {
        ybg[g] = (unsigned*)(smem + OFF_YB) + (g * 32 + lane) * 52;
        hbg[g] = (unsigned*)(smem + OFF_HB) + (g * 32 + lane) * 52;
    }

    // ---- y master state (owned tiles: complex 2e,2e+1; real 16+e) x 2 groups ----
    int rows[2];
    rows[0] = blockIdx.x * 32 + (lane >> 2);
    rows[1] = rows[0] + 16;
    float ymc[2][2][4];   // [tile n][group][r0c0, r0c1, r1c0, r1c1]
    float ymr[2][4];      // [group][...]
#pragma unroll
    for (int g = 0; g < 2; ++g) {
        const float* x0 = x + (size_t)rows[g] * 12288;
        const float* x1 = x0 + 8 * 12288;
#pragma unroll
        for (int n = 0; n < 2; ++n) {
            int col = 8 * (2 * e + n) + colb;
            float2 v0 = *(const float2*)(x0 + col);
            float2 v1 = *(const float2*)(x1 + col);
            ymc[n][g][0] = v0.x; ymc[n][g][1] = v0.y;
            ymc[n][g][2] = v1.x; ymc[n][g][3] = v1.y;
        }
        int colr = 128 + 8 * e + colb;
        float2 v0 = *(const float2*)(x0 + colr);
        float2 v1 = *(const float2*)(x1 + colr);
        ymr[g][0] = v0.x; ymr[g][1] = v0.y; ymr[g][2] = v1.x; ymr[g][3] = v1.y;
        // publish initial y fragments
#pragma unroll
        for (int n = 0; n < 2; ++n) {
            uint2 f;
            f.x = pbf(ymc[n][g][0], ymc[n][g][1]);
            f.y = pbf(ymc[n][g][2], ymc[n][g][3]);
            *(uint2*)(ybg[g] + 2 * (2 * e + n)) = f;
        }
        uint2 fr;
        fr.x = pbf(ymr[g][0], ymr[g][1]);
        fr.y = pbf(ymr[g][2], ymr[g][3]);
        *(uint2*)(ybg[g] + 2 * (16 + e)) = fr;
    }
    __syncthreads();

#pragma unroll 1
    for (int t = 0; t < 64; ++t) {
        // ===== MMA1: h1 n-tiles 3e..3e+2, K=192, both row-groups =====
        float a1[3][2][4];
#pragma unroll
        for (int n = 0; n < 3; ++n)
#pragma unroll
            for (int g = 0; g < 2; ++g)
#pragma unroll
                for (int v = 0; v < 4; ++v) a1[n][g][v] = 0.0f;
#pragma unroll
        for (int k = 0; k < 12; ++k) {
#pragma unroll
            for (int g = 0; g < 2; ++g) {
                uint4 av = *(const uint4*)(ybg[g] + 4 * k);
                MMA(a1[0][g], av.x, av.y, av.z, av.w, B1[k][0][0], B1[k][0][1]);
                MMA(a1[1][g], av.x, av.y, av.z, av.w, B1[k][1][0], B1[k][1][1]);
                MMA(a1[2][g], av.x, av.y, av.z, av.w, B1[k][2][0], B1[k][2][1]);
            }
        }
        // h1 = relu(. + b1) -> publish bf16 frags
#pragma unroll
        for (int n = 0; n < 3; ++n) {
            int gn = 3 * e + n;
#pragma unroll
            for (int g = 0; g < 2; ++g) {
                uint2 f;
                f.x = pbf(fmaxf(a1[n][g][0] + bc1[n].x, 0.0f),
                          fmaxf(a1[n][g][1] + bc1[n].y, 0.0f));
                f.y = pbf(fmaxf(a1[n][g][2] + bc1[n].x, 0.0f),
                          fmaxf(a1[n][g][3] + bc1[n].y, 0.0f));
                *(uint2*)(hbg[g] + 2 * gn) = f;
            }
        }
        __syncthreads();

        // ===== MMA2: complex tiles 2e..2e+1 (K=128), real tile e (K=64) =====
        float a2c[2][2][4], a2r[2][4];
#pragma unroll
        for (int n = 0; n < 2; ++n)
#pragma unroll
            for (int g = 0; g < 2; ++g)
#pragma unroll
                for (int v = 0; v < 4; ++v) { a2c[n][g][v] = 0.0f; a2r[g][v] = 0.0f; }
#pragma unroll
        for (int k = 0; k < 8; ++k) {
#pragma unroll
            for (int g = 0; g < 2; ++g) {
                uint4 av = *(const uint4*)(hbg[g] + 4 * k);
                MMA(a2c[0][g], av.x, av.y, av.z, av.w, B2c[k][0][0], B2c[k][0][1]);
                MMA(a2c[1][g], av.x, av.y, av.z, av.w, B2c[k][1][0], B2c[k][1][1]);
            }
        }
#pragma unroll
        for (int k = 0; k < 4; ++k) {
#pragma unroll
            for (int g = 0; g < 2; ++g) {
                uint4 av = *(const uint4*)(hbg[g] + 32 + 4 * k);
                MMA(a2r[g], av.x, av.y, av.z, av.w, B2r[k][0], B2r[k][1]);
            }
        }

        // ===== epilogue: state update + out + publish new y frags =====
#pragma unroll
        for (int g = 0; g < 2; ++g) {
            float* o0 = out + (size_t)rows[g] * 12288 + t * 192;
            float* o1 = o0 + 8 * 12288;
#pragma unroll
            for (int n = 0; n < 2; ++n) {   // complex: even col = mu, odd = omega
                int col = 8 * (2 * e + n) + colb;
                float e0 = __expf(0.01f * (a2c[n][g][0] + bc2[n].x));
                float s0, c0;
                __sincosf(0.01f * (a2c[n][g][1] + bc2[n].y), &s0, &c0);
                float ye = ymc[n][g][0], yo = ymc[n][g][1];
                ymc[n][g][0] = e0 * (c0 * ye - s0 * yo);
                ymc[n][g][1] = e0 * (s0 * ye + c0 * yo);
                float e1 = __expf(0.01f * (a2c[n][g][2] + bc2[n].x));
                float s1, c1;
                __sincosf(0.01f * (a2c[n][g][3] + bc2[n].y), &s1, &c1);
                ye = ymc[n][g][2]; yo = ymc[n][g][3];
                ymc[n][g][2] = e1 * (c1 * ye - s1 * yo);
                ymc[n][g][3] = e1 * (s1 * ye + c1 * yo);
                *(float2*)(o0 + col) = make_float2(ymc[n][g][0], ymc[n][g][1]);
                *(float2*)(o1 + col) = make_float2(ymc[n][g][2], ymc[n][g][3]);
                uint2 f;
                f.x = pbf(ymc[n][g][0], ymc[n][g][1]);
                f.y = pbf(ymc[n][g][2], ymc[n][g][3]);
                *(uint2*)(ybg[g] + 2 * (2 * e + n)) = f;
            }
            {   // real diagonal
                int col = 128 + 8 * e + colb;
                ymr[g][0] *= __expf(0.01f * (a2r[g][0] + br2.x));
                ymr[g][1] *= __expf(0.01f * (a2r[g][1] + br2.y));
                ymr[g][2] *= __expf(0.01f * (a2r[g][2] + br2.x));
                ymr[g][3] *= __expf(0.01f * (a2r[g][3] + br2.y));
                *(float2*)(o0 + col) = make_float2(ymr[g][0], ymr[g][1]);
                *(float2*)(o1 + col) = make_float2(ymr[g][2], ymr[g][3]);
                uint2 f;
                f.x = pbf(ymr[g][0], ymr[g][1]);
                f.y = pbf(ymr[g][2], ymr[g][3]);
                *(uint2*)(ybg[g] + 2 * (16 + e)) = f;
            }
        }
        __syncthreads();
    }
}

extern "C" void kernel_launch(void* const* d_in, const int* in_sizes, int n_in,
                              void* d_out, int out_size)
{
    (void)in_sizes; (void)n_in; (void)out_size;
    cudaFuncSetAttribute(koopman_rw_kernel,
                         cudaFuncAttributeMaxDynamicSharedMemorySize, SMEM_BYTES);
    koopman_rw_kernel<<<128, 256, SMEM_BYTES>>>(
        (const float*)d_in[0],
        (const float*)d_in[1], (const float*)d_in[2],
        (const float*)d_in[3], (const float*)d_in[4],
        (const float*)d_in[5], (const float*)d_in[6],
        (const float*)d_in[7], (const float*)d_in[8],
        (float*)d_out);
}